// round 15
// baseline (speedup 1.0000x reference)
#include <cuda_runtime.h>
#include <cuda_bf16.h>
#include <cstddef>

// ---------------------------------------------------------------------------
// RRN: all-pairs message MLP -> sum -> g MLP -> 1-step LSTM -> output MLP
// B=16, N=128, H=M=128.
//   layer-1 of the pair MLP factorizes:
//     pre1[b,i,j,:] = hidden[b,j] @ f_w0[:, :128]^T          (A,  per (b,j))
//                   + hidden[b,i] @ f_w0[:, 128:]^T + f_b0   (Bm, per (b,i))
//   H1 built on the fly inside the H2 GEMM (never materialized).
//   MSG reduced over j inside the MSG GEMM epilogue (never materialized;
//   128-row tile = full j group, so S is written directly).
//   g-MLP layer 0 concat folded via weight split (two-pass GEMM, no XG).
//   H2 + MSG GEMMs on tensor cores (tf32 mma.sync.m16n8k8, fp32 accum),
//   128x128 tiles, single smem buffer + register-staged prefetch.
//   SIMT tail GEMMs: COLS=128 tiles, 128-256 blocks -> ~87-100% SM coverage.
// ---------------------------------------------------------------------------

#define Bv   16
#define Nv   128
#define Hv   128
#define BN   (Bv * Nv)          // 2048
#define P    (BN * Nv)          // 262144 pairs

// output layout: out[16*64], out_g[2048*128], h_n[2048*128], c_n[2048*128]
#define OFF_OUT   0
#define OFF_OUTG  1024
#define OFF_HN    (1024 + BN * Hv)
#define OFF_CN    (1024 + 2 * BN * Hv)

// -------------------- device scratch (no allocations allowed) --------------
__device__ float g_A    [BN * 256];
__device__ float g_Bm   [BN * 256];
__device__ float g_H2   [(size_t)P * 256];   // 256 MB
__device__ float g_S    [BN * 128];
__device__ float g_T0   [BN * 256];
__device__ float g_T1   [BN * 256];
__device__ float g_G    [BN * 128];
__device__ float g_GT   [BN * 512];
__device__ float g_SH   [Bv * 128];
__device__ float g_O0   [Bv * 256];

// -------------------- tf32 helpers -----------------------------------------
__device__ __forceinline__ unsigned f2tf(float x) {
    unsigned u;
    asm("cvt.rna.tf32.f32 %0, %1;" : "=r"(u) : "f"(x));
    return u;
}

// D += A@B, m16n8k8 tf32, fp32 accumulate. Standard fragment layout:
//  a0:(g,tg) a1:(g+8,tg) a2:(g,tg+4) a3:(g+8,tg+4)   [g=lane>>2, tg=lane&3]
//  b0:(k=tg,n=g) b1:(k=tg+4,n=g)
//  c0:(g,2tg) c1:(g,2tg+1) c2:(g+8,2tg) c3:(g+8,2tg+1)
__device__ __forceinline__ void mma8(float* c, const unsigned* a, const unsigned* b) {
    asm volatile(
        "mma.sync.aligned.m16n8k8.row.col.f32.tf32.tf32.f32 "
        "{%0,%1,%2,%3}, {%4,%5,%6,%7}, {%8,%9}, {%0,%1,%2,%3};"
        : "+f"(c[0]), "+f"(c[1]), "+f"(c[2]), "+f"(c[3])
        : "r"(a[0]), "r"(a[1]), "r"(a[2]), "r"(a[3]), "r"(b[0]), "r"(b[1]));
}

// -------------------- generic tiled GEMM (small GEMMs only) ----------------
// Block tile: 32 rows x COLS cols, 256 threads, panel-streamed K (32-wide).
template <int COLS>
__global__ __launch_bounds__(256)
void gemm_kernel(const float* __restrict__ X, int ldX,
                 const float* __restrict__ W, int ldW, int wOff,
                 const float* __restrict__ bias,
                 float* __restrict__ Y, int ldY,
                 int rows, int K, int Nout, int doRelu, int doAcc)
{
    constexpr int TGC = COLS / 4;
    constexpr int RPT = 32 / (256 / TGC);
    __shared__ float sX[32][36];
    __shared__ __align__(16) float sW[32][COLS + 4];

    const int t = threadIdx.x;
    const int rowBase = blockIdx.x * 32;
    const int colBase = blockIdx.y * COLS;

    const int tr = t / TGC;
    const int tc = t - tr * TGC;
    const int r0 = tr * RPT;

    float acc[RPT][4];
#pragma unroll
    for (int i = 0; i < RPT; i++)
#pragma unroll
        for (int j = 0; j < 4; j++) acc[i][j] = 0.f;

    for (int k0 = 0; k0 < K; k0 += 32) {
        __syncthreads();
        {
            int r = t >> 5, kk = t & 31;
#pragma unroll
            for (int rep = 0; rep < 4; rep++, r += 8) {
                int gr = rowBase + r;
                sX[r][kk] = (gr < rows) ? X[(size_t)gr * ldX + k0 + kk] : 0.f;
            }
        }
        for (int idx = t; idx < 32 * COLS; idx += 256) {
            int c = idx >> 5, kk = idx & 31;
            int gc = colBase + c;
            sW[kk][c] = (gc < Nout) ? W[(size_t)gc * ldW + wOff + k0 + kk] : 0.f;
        }
        __syncthreads();
#pragma unroll
        for (int kk = 0; kk < 32; kk++) {
            float4 wv = *(const float4*)&sW[kk][tc * 4];
#pragma unroll
            for (int rr = 0; rr < RPT; rr++) {
                float xv = sX[r0 + rr][kk];
                acc[rr][0] = fmaf(xv, wv.x, acc[rr][0]);
                acc[rr][1] = fmaf(xv, wv.y, acc[rr][1]);
                acc[rr][2] = fmaf(xv, wv.z, acc[rr][2]);
                acc[rr][3] = fmaf(xv, wv.w, acc[rr][3]);
            }
        }
    }

#pragma unroll
    for (int rr = 0; rr < RPT; rr++) {
        int gr = rowBase + r0 + rr;
        if (gr >= rows) continue;
#pragma unroll
        for (int cc = 0; cc < 4; cc++) {
            int gc = colBase + tc * 4 + cc;
            if (gc >= Nout) continue;
            float v = acc[rr][cc];
            if (bias) v += bias[gc];
            if (doAcc) v += Y[(size_t)gr * ldY + gc];
            if (doRelu) v = fmaxf(v, 0.f);
            Y[(size_t)gr * ldY + gc] = v;
        }
    }
}

// -------------------- H2 GEMM (tensor cores, 128x128 tile) -----------------
// H2[p] = relu( relu(A[b,j] + Bm[b,i]) @ f_w1^T + f_b1 ),  p = bi*128 + j.
// One block = one full bi group (128 rows) x 128 cols. 512 thr, 16 warps
// (4M x 4N), warp tile 32x32. Single smem buffer; next panel register-
// staged before the barrier, committed after a post-MMA barrier.
// smem stride 36 words: stores (col=lane) and fragment loads (4g+tg)
// conflict-free.
__global__ __launch_bounds__(512)
void gemm_h2_tc(const float* __restrict__ A, const float* __restrict__ Bm,
                const float* __restrict__ W, const float* __restrict__ bias,
                float* __restrict__ Y)
{
    __shared__ unsigned sA[128][36];   // [m][k] tf32 bits
    __shared__ unsigned sW[128][36];   // [n][k] tf32 bits

    const int t = threadIdx.x;
    const int bi = blockIdx.x;               // 128-row tile = whole bi group
    const int b  = bi >> 7;
    const size_t rowBase = (size_t)bi * 128;
    const int colBase = blockIdx.y * 128;

    const int warp = t >> 5, lane = t & 31;
    const int wm = warp >> 2, wn = warp & 3;
    const int g = lane >> 2, tg = lane & 3;
    const int kk  = t & 31;                  // load lane: k within panel
    const int rr0 = t >> 5;                  // load lane: row 0..15 (stride 16)

    const float* Abase = A + (size_t)(b * 128) * 256 + kk;   // j rows
    const float* Wbase = W + (size_t)colBase * 256 + kk;
    const float* BmB   = Bm + (size_t)bi * 256 + kk;

    float ra[8], rw[8], bmv, nbmv;
    float na[8], nw[8];
    float acc[2][4][4];                      // [mf][nf][c]
#pragma unroll
    for (int i = 0; i < 2; i++)
#pragma unroll
        for (int j = 0; j < 4; j++)
#pragma unroll
            for (int k = 0; k < 4; k++) acc[i][j][k] = 0.f;

    // Prologue: load panel 0 into registers.
    bmv = BmB[0];
#pragma unroll
    for (int rep = 0; rep < 8; rep++) {
        ra[rep] = Abase[(size_t)(rr0 + 16 * rep) * 256];
        rw[rep] = Wbase[(size_t)(rr0 + 16 * rep) * 256];
    }

#pragma unroll
    for (int p = 0; p < 8; p++) {
        // Commit staged panel p to smem (cvt at store).
#pragma unroll
        for (int rep = 0; rep < 8; rep++) {
            sA[rr0 + 16 * rep][kk] = f2tf(fmaxf(ra[rep] + bmv, 0.f));
            sW[rr0 + 16 * rep][kk] = f2tf(rw[rep]);
        }
        // Prefetch panel p+1 BEFORE the barrier (register-only, order-safe).
        if (p < 7) {
            int k0 = (p + 1) * 32;
            nbmv = BmB[k0];
#pragma unroll
            for (int rep = 0; rep < 8; rep++) {
                na[rep] = Abase[(size_t)(rr0 + 16 * rep) * 256 + k0];
                nw[rep] = Wbase[(size_t)(rr0 + 16 * rep) * 256 + k0];
            }
        }
        __syncthreads();                     // STS(p) visible
        // MMAs on panel p.
#pragma unroll
        for (int ks = 0; ks < 4; ks++) {
            const int kc = ks * 8;
            unsigned a[2][4], bb[4][2];
#pragma unroll
            for (int mf = 0; mf < 2; mf++) {
                int rb = wm * 32 + mf * 16 + g;
                a[mf][0] = sA[rb][kc + tg];
                a[mf][1] = sA[rb + 8][kc + tg];
                a[mf][2] = sA[rb][kc + tg + 4];
                a[mf][3] = sA[rb + 8][kc + tg + 4];
            }
#pragma unroll
            for (int nf = 0; nf < 4; nf++) {
                int nn = wn * 32 + nf * 8 + g;
                bb[nf][0] = sW[nn][kc + tg];
                bb[nf][1] = sW[nn][kc + tg + 4];
            }
#pragma unroll
            for (int mf = 0; mf < 2; mf++)
#pragma unroll
                for (int nf = 0; nf < 4; nf++)
                    mma8(acc[mf][nf], a[mf], bb[nf]);
        }
        __syncthreads();                     // all reads done before next STS
        if (p < 7) {
            bmv = nbmv;
#pragma unroll
            for (int rep = 0; rep < 8; rep++) { ra[rep] = na[rep]; rw[rep] = nw[rep]; }
        }
    }

#pragma unroll
    for (int mf = 0; mf < 2; mf++) {
        size_t r0g = rowBase + wm * 32 + mf * 16 + g;
#pragma unroll
        for (int nf = 0; nf < 4; nf++) {
            int c0 = colBase + wn * 32 + nf * 8 + 2 * tg;
            float b0v = bias[c0], b1v = bias[c0 + 1];
            float2 v0 = make_float2(fmaxf(acc[mf][nf][0] + b0v, 0.f),
                                    fmaxf(acc[mf][nf][1] + b1v, 0.f));
            float2 v1 = make_float2(fmaxf(acc[mf][nf][2] + b0v, 0.f),
                                    fmaxf(acc[mf][nf][3] + b1v, 0.f));
            *(float2*)&Y[r0g * 256 + c0]       = v0;
            *(float2*)&Y[(r0g + 8) * 256 + c0] = v1;
        }
    }
}

// -------------------- MSG GEMM (tensor cores, 128x128) + full j-sum --------
// e[p][c] = relu(H2[p] @ f_w2^T + f_b2); block covers all 128 cols and the
// full 128-row bi group -> S[bi] written directly (no partials).
__global__ __launch_bounds__(512)
void gemm_msg_tc(const float* __restrict__ X,    // H2
                 const float* __restrict__ W,    // f_w2 [128,256]
                 const float* __restrict__ bias,
                 float* __restrict__ S)
{
    __shared__ unsigned sA[128][36];
    __shared__ unsigned sW[128][36];
    __shared__ float sRed[4][128];

    const int t = threadIdx.x;
    const int bi = blockIdx.x;
    const size_t rowBase = (size_t)bi * 128;

    const int warp = t >> 5, lane = t & 31;
    const int wm = warp >> 2, wn = warp & 3;
    const int g = lane >> 2, tg = lane & 3;
    const int kk  = t & 31;
    const int rr0 = t >> 5;

    const float* Xbase = X + rowBase * 256 + kk;
    const float* Wbase = W + kk;             // all 128 rows of f_w2

    float ra[8], rw[8], na[8], nw[8];
    float acc[2][4][4];
#pragma unroll
    for (int i = 0; i < 2; i++)
#pragma unroll
        for (int j = 0; j < 4; j++)
#pragma unroll
            for (int k = 0; k < 4; k++) acc[i][j][k] = 0.f;

#pragma unroll
    for (int rep = 0; rep < 8; rep++) {
        ra[rep] = Xbase[(size_t)(rr0 + 16 * rep) * 256];
        rw[rep] = Wbase[(size_t)(rr0 + 16 * rep) * 256];
    }

#pragma unroll
    for (int p = 0; p < 8; p++) {
#pragma unroll
        for (int rep = 0; rep < 8; rep++) {
            sA[rr0 + 16 * rep][kk] = f2tf(ra[rep]);
            sW[rr0 + 16 * rep][kk] = f2tf(rw[rep]);
        }
        if (p < 7) {
            int k0 = (p + 1) * 32;
#pragma unroll
            for (int rep = 0; rep < 8; rep++) {
                na[rep] = Xbase[(size_t)(rr0 + 16 * rep) * 256 + k0];
                nw[rep] = Wbase[(size_t)(rr0 + 16 * rep) * 256 + k0];
            }
        }
        __syncthreads();
#pragma unroll
        for (int ks = 0; ks < 4; ks++) {
            const int kc = ks * 8;
            unsigned a[2][4], bb[4][2];
#pragma unroll
            for (int mf = 0; mf < 2; mf++) {
                int rb = wm * 32 + mf * 16 + g;
                a[mf][0] = sA[rb][kc + tg];
                a[mf][1] = sA[rb + 8][kc + tg];
                a[mf][2] = sA[rb][kc + tg + 4];
                a[mf][3] = sA[rb + 8][kc + tg + 4];
            }
#pragma unroll
            for (int nf = 0; nf < 4; nf++) {
                int nn = wn * 32 + nf * 8 + g;
                bb[nf][0] = sW[nn][kc + tg];
                bb[nf][1] = sW[nn][kc + tg + 4];
            }
#pragma unroll
            for (int mf = 0; mf < 2; mf++)
#pragma unroll
                for (int nf = 0; nf < 4; nf++)
                    mma8(acc[mf][nf], a[mf], bb[nf]);
        }
        __syncthreads();
        if (p < 7) {
#pragma unroll
            for (int rep = 0; rep < 8; rep++) { ra[rep] = na[rep]; rw[rep] = nw[rep]; }
        }
    }

    // Epilogue: relu(acc+bias); warp sums its 32 rows per column via shfl
    // butterfly over g; then the 4 wm partials combine in smem; S direct.
#pragma unroll
    for (int nf = 0; nf < 4; nf++) {
        int cl = wn * 32 + nf * 8 + 2 * tg;       // column 0..127
        float b0v = bias[cl], b1v = bias[cl + 1];
        float v0 = fmaxf(acc[0][nf][0] + b0v, 0.f) + fmaxf(acc[0][nf][2] + b0v, 0.f)
                 + fmaxf(acc[1][nf][0] + b0v, 0.f) + fmaxf(acc[1][nf][2] + b0v, 0.f);
        float v1 = fmaxf(acc[0][nf][1] + b1v, 0.f) + fmaxf(acc[0][nf][3] + b1v, 0.f)
                 + fmaxf(acc[1][nf][1] + b1v, 0.f) + fmaxf(acc[1][nf][3] + b1v, 0.f);
#pragma unroll
        for (int off = 4; off < 32; off <<= 1) {
            v0 += __shfl_xor_sync(0xffffffffu, v0, off);
            v1 += __shfl_xor_sync(0xffffffffu, v1, off);
        }
        if (g == 0) {
            sRed[wm][cl]     = v0;
            sRed[wm][cl + 1] = v1;
        }
    }
    __syncthreads();
    if (t < 128)
        S[(size_t)bi * 128 + t] = sRed[0][t] + sRed[1][t] + sRed[2][t] + sRed[3][t];
}

__device__ __forceinline__ float sigmoidf_(float v) {
    return 1.f / (1.f + expf(-v));
}

// -------------------- LSTM elementwise; writes out_g, h_n, c_n -------------
__global__ __launch_bounds__(128)
void lstm_kernel(const float* __restrict__ gates, const float* __restrict__ c0,
                 float* __restrict__ out)
{
    int r = blockIdx.x, c = threadIdx.x;
    const float* g = gates + (size_t)r * 512;
    float ig = g[c], fg = g[128 + c], gg = g[256 + c], og = g[384 + c];
    float cn = sigmoidf_(fg) * c0[(size_t)r * 128 + c] + sigmoidf_(ig) * tanhf(gg);
    float hn = sigmoidf_(og) * tanhf(cn);
    size_t idx = (size_t)r * 128 + c;
    out[OFF_OUTG + idx] = hn;
    out[OFF_HN   + idx] = hn;
    out[OFF_CN   + idx] = cn;
}

// -------------------- sum_hidden[b][h] = sum_i h_n[b,i,h] ------------------
__global__ __launch_bounds__(128)
void sum_hidden_kernel(const float* __restrict__ HN, float* __restrict__ SH)
{
    int b = blockIdx.x, c = threadIdx.x;
    float s = 0.f;
#pragma unroll 8
    for (int i = 0; i < 128; i++) s += HN[(size_t)(b * 128 + i) * 128 + c];
    SH[b * 128 + c] = s;
}

// ---------------------------------------------------------------------------
extern "C" void kernel_launch(void* const* d_in, const int* in_sizes, int n_in,
                              void* d_out, int out_size)
{
    const float* x      = (const float*)d_in[0];
    const float* hidden = (const float*)d_in[1];
    const float* h0     = (const float*)d_in[2];
    const float* c0     = (const float*)d_in[3];
    const float* f_w0   = (const float*)d_in[4];
    const float* f_b0   = (const float*)d_in[5];
    const float* f_w1   = (const float*)d_in[6];
    const float* f_b1   = (const float*)d_in[7];
    const float* f_w2   = (const float*)d_in[8];
    const float* f_b2   = (const float*)d_in[9];
    const float* g_w0   = (const float*)d_in[10];
    const float* g_b0   = (const float*)d_in[11];
    const float* g_w1   = (const float*)d_in[12];
    const float* g_b1   = (const float*)d_in[13];
    const float* g_w2   = (const float*)d_in[14];
    const float* g_b2   = (const float*)d_in[15];
    const float* wih    = (const float*)d_in[16];
    const float* whh    = (const float*)d_in[17];
    const float* bih    = (const float*)d_in[18];
    const float* bhh    = (const float*)d_in[19];
    const float* o_w0   = (const float*)d_in[20];
    const float* o_b0   = (const float*)d_in[21];
    const float* o_w1   = (const float*)d_in[22];
    const float* o_b1   = (const float*)d_in[23];
    float* out = (float*)d_out;

    float *A, *Bm, *H2, *S, *T0, *T1, *G, *GT, *SH, *O0;
    cudaGetSymbolAddress((void**)&A,  g_A);
    cudaGetSymbolAddress((void**)&Bm, g_Bm);
    cudaGetSymbolAddress((void**)&H2, g_H2);
    cudaGetSymbolAddress((void**)&S,  g_S);
    cudaGetSymbolAddress((void**)&T0, g_T0);
    cudaGetSymbolAddress((void**)&T1, g_T1);
    cudaGetSymbolAddress((void**)&G,  g_G);
    cudaGetSymbolAddress((void**)&GT, g_GT);
    cudaGetSymbolAddress((void**)&SH, g_SH);
    cudaGetSymbolAddress((void**)&O0, g_O0);

    // 1) Factorized layer-1 halves. COLS=128, grid (64,2): 128 blocks.
    gemm_kernel<128><<<dim3(BN / 32, 2), 256>>>(hidden, 128, f_w0, 256, 0,
                                                nullptr, A, 256, BN, 128, 256, 0, 0);
    gemm_kernel<128><<<dim3(BN / 32, 2), 256>>>(hidden, 128, f_w0, 256, 128,
                                                f_b0, Bm, 256, BN, 128, 256, 0, 0);

    // 2) H2 = relu(relu(A+Bm) @ f_w1^T + f_b1)  [262144 x 256], tensor cores.
    gemm_h2_tc<<<dim3(BN, 2), 512>>>(A, Bm, f_w1, f_b1, H2);

    // 3) MSG GEMM (tensor cores) + full j-sum -> S directly.
    gemm_msg_tc<<<BN, 512>>>(H2, f_w2, f_b2, S);

    // 4) g-MLP. Layer 0 concat folded via weight split (two-pass, like the
    //    LSTM gates): T0 = relu(x @ g_w0[:,:128]^T + S @ g_w0[:,128:]^T + b).
    gemm_kernel<128><<<dim3(BN / 32, 2), 256>>>(x, 128, g_w0, 256, 0,
                                                nullptr, T0, 256, BN, 128, 256, 0, 0);
    gemm_kernel<128><<<dim3(BN / 32, 2), 256>>>(S, 128, g_w0, 256, 128,
                                                g_b0, T0, 256, BN, 128, 256, 1, 1);
    gemm_kernel<128><<<dim3(BN / 32, 2), 256>>>(T0, 256, g_w1, 256, 0,
                                                g_b1, T1, 256, BN, 256, 256, 1, 0);
    gemm_kernel<128><<<dim3(BN / 32, 1), 256>>>(T1, 256, g_w2, 256, 0,
                                                g_b2, G, 128, BN, 256, 128, 1, 0);

    // 5) LSTM gates = G @ wih^T + bih + h0 @ whh^T + bhh   [2048 x 512]
    gemm_kernel<128><<<dim3(BN / 32, 4), 256>>>(G, 128, wih, 128, 0,
                                                bih, GT, 512, BN, 128, 512, 0, 0);
    gemm_kernel<128><<<dim3(BN / 32, 4), 256>>>(h0, 128, whh, 128, 0,
                                                bhh, GT, 512, BN, 128, 512, 0, 1);

    // 6) LSTM nonlinearity -> out_g, h_n, c_n
    lstm_kernel<<<BN, 128>>>(GT, c0, out);

    // 7) sum over nodes, then output MLP -> out[16 x 64]
    sum_hidden_kernel<<<Bv, 128>>>(out + OFF_HN, SH);
    gemm_kernel<128><<<dim3(1, 2), 256>>>(SH, 128, o_w0, 128, 0,
                                          o_b0, O0, 256, Bv, 128, 256, 1, 0);
    gemm_kernel<64><<<dim3(1, 1), 256>>>(O0, 256, o_w1, 256, 0,
                                         o_b1, out + OFF_OUT, 64, Bv, 256, 64, 1, 0);
}